// round 1
// baseline (speedup 1.0000x reference)
#include <cuda_runtime.h>
#include <cstdint>

#define D        512
#define NN       50000
#define NE       200000
#define NG       2048
#define NL       5
#define HID      (2 * D)

// ---------------- scratch (device globals; no allocations allowed) ----------
__device__ float g_h[(size_t)NN * D];          // node features
__device__ float g_agg[(size_t)NN * D];        // aggregated messages
__device__ float g_hidden[(size_t)NN * HID];   // GIN MLP hidden
__device__ float g_pooled[(size_t)NG * D];     // mean-pooled graph features
__device__ float g_ptmp[(size_t)NG * D];       // projection hidden

// ---------------- f32x2 packed-FMA helpers (2x FFMA throughput on sm_103a) --
__device__ __forceinline__ uint64_t pack2(float lo, float hi) {
    uint64_t r;
    asm("mov.b64 %0, {%1, %2};" : "=l"(r) : "f"(lo), "f"(hi));
    return r;
}
__device__ __forceinline__ uint64_t dup2(float v) {
    uint64_t r;
    asm("mov.b64 %0, {%1, %1};" : "=l"(r) : "f"(v));
    return r;
}
__device__ __forceinline__ void fma2(uint64_t& d, uint64_t a, uint64_t b) {
    asm("fma.rn.f32x2 %0, %1, %2, %0;" : "+l"(d) : "l"(a), "l"(b));
}
__device__ __forceinline__ float2 unpack2(uint64_t v) {
    float2 r;
    asm("mov.b64 {%0, %1}, %2;" : "=f"(r.x), "=f"(r.y) : "l"(v));
    return r;
}

// ---------------- atom encoder: h = atom_emb1[x0] + atom_emb2[x1] -----------
__global__ void k_atom(const int* __restrict__ x,
                       const float* __restrict__ e1,
                       const float* __restrict__ e2) {
    int v = blockIdx.x;
    int t = threadIdx.x;                 // 128 threads, float4 each
    int a = x[2 * v], c = x[2 * v + 1];
    float4 u = ((const float4*)(e1 + (size_t)a * D))[t];
    float4 w = ((const float4*)(e2 + (size_t)c * D))[t];
    ((float4*)(g_h + (size_t)v * D))[t] =
        make_float4(u.x + w.x, u.y + w.y, u.z + w.z, u.w + w.w);
}

// ---------------- agg init: self-loop message h[v] + e_loop -----------------
__global__ void k_init_agg(const float* __restrict__ be1,
                           const float* __restrict__ be2) {
    int v = blockIdx.x;
    int t = threadIdx.x;
    float4 l1 = ((const float4*)(be1 + 6 * D))[t];   // bond type 6
    float4 l2 = ((const float4*)(be2 + 3 * D))[t];   // bond dir 3
    float4 hv = ((const float4*)(g_h + (size_t)v * D))[t];
    ((float4*)(g_agg + (size_t)v * D))[t] =
        make_float4(hv.x + l1.x + l2.x, hv.y + l1.y + l2.y,
                    hv.z + l1.z + l2.z, hv.w + l1.w + l2.w);
}

// ---------------- edge scatter: agg[dst] += h[src] + e ----------------------
__global__ void k_scatter(const int* __restrict__ ei,
                          const int* __restrict__ ea,
                          const float* __restrict__ be1,
                          const float* __restrict__ be2) {
    int e = blockIdx.x;
    int t = threadIdx.x;
    int src = ei[e];
    int dst = ei[NE + e];
    int a0 = ea[2 * e], a1 = ea[2 * e + 1];
    float4 hv = ((const float4*)(g_h + (size_t)src * D))[t];
    float4 v1 = ((const float4*)(be1 + (size_t)a0 * D))[t];
    float4 v2 = ((const float4*)(be2 + (size_t)a1 * D))[t];
    float* p = g_agg + (size_t)dst * D + t * 4;
    atomicAdd(p + 0, hv.x + v1.x + v2.x);
    atomicAdd(p + 1, hv.y + v1.y + v2.y);
    atomicAdd(p + 2, hv.z + v1.z + v2.z);
    atomicAdd(p + 3, hv.w + v1.w + v2.w);
}

// ---------------- GEMM: C = [relu](A @ B + bias) ----------------------------
// A [M,K] row-major, B [K,N] row-major, C [M,N]. 128x128x16 tile, 256 thr,
// 8x8 microtile per thread, f32x2 packed FMA accumulators.
#define BM 128
#define BN 128
#define BK 16

template <bool RELU>
__global__ __launch_bounds__(256, 2)
void k_gemm(const float* __restrict__ A, const float* __restrict__ B,
            const float* __restrict__ bias, float* __restrict__ C,
            int M, int N, int K) {
    __shared__ float As[BK][BM];
    __shared__ float Bs[BK][BN];

    const int tid = threadIdx.x;
    const int tx = tid & 15;     // 16 n-positions
    const int ty = tid >> 4;     // 16 m-positions
    const int m0 = blockIdx.x * BM;
    const int n0 = blockIdx.y * BN;

    uint64_t acc[8][4];
#pragma unroll
    for (int i = 0; i < 8; i++)
#pragma unroll
        for (int j = 0; j < 4; j++) acc[i][j] = 0ull;

    for (int k0 = 0; k0 < K; k0 += BK) {
        // A tile: 128 rows x 16 cols -> As[k][m] (transposed, conflict-free)
#pragma unroll
        for (int it = 0; it < 2; it++) {
            int idx = tid + it * 256;
            int row = idx & 127;
            int seg = idx >> 7;          // 0..3, 4 floats each
            int gm = m0 + row;
            float4 v = make_float4(0.f, 0.f, 0.f, 0.f);
            if (gm < M)
                v = *(const float4*)(A + (size_t)gm * K + k0 + seg * 4);
            As[seg * 4 + 0][row] = v.x;
            As[seg * 4 + 1][row] = v.y;
            As[seg * 4 + 2][row] = v.z;
            As[seg * 4 + 3][row] = v.w;
        }
        // B tile: 16 rows x 128 cols, coalesced float4
#pragma unroll
        for (int it = 0; it < 2; it++) {
            int idx = tid + it * 256;
            int row = idx >> 5;
            int colv = idx & 31;
            *(float4*)&Bs[row][colv * 4] =
                *(const float4*)(B + (size_t)(k0 + row) * N + n0 + colv * 4);
        }
        __syncthreads();

#pragma unroll
        for (int kk = 0; kk < BK; kk++) {
            float4 a03 = *(const float4*)&As[kk][ty * 4];
            float4 a47 = *(const float4*)&As[kk][64 + ty * 4];
            float4 b0  = *(const float4*)&Bs[kk][tx * 4];
            float4 b1  = *(const float4*)&Bs[kk][64 + tx * 4];
            uint64_t bp[4] = {pack2(b0.x, b0.y), pack2(b0.z, b0.w),
                              pack2(b1.x, b1.y), pack2(b1.z, b1.w)};
            float av[8] = {a03.x, a03.y, a03.z, a03.w,
                           a47.x, a47.y, a47.z, a47.w};
#pragma unroll
            for (int i = 0; i < 8; i++) {
                uint64_t ad = dup2(av[i]);
#pragma unroll
                for (int j = 0; j < 4; j++) fma2(acc[i][j], ad, bp[j]);
            }
        }
        __syncthreads();
    }

    const int nc0 = n0 + tx * 4;
    const int nc1 = n0 + 64 + tx * 4;
    float4 bi0 = *(const float4*)(bias + nc0);
    float4 bi1 = *(const float4*)(bias + nc1);
#pragma unroll
    for (int i = 0; i < 8; i++) {
        int gm = m0 + ((i < 4) ? (ty * 4 + i) : (64 + ty * 4 + (i - 4)));
        if (gm >= M) continue;
        float2 p0 = unpack2(acc[i][0]);
        float2 p1 = unpack2(acc[i][1]);
        float2 p2 = unpack2(acc[i][2]);
        float2 p3 = unpack2(acc[i][3]);
        float4 c0 = make_float4(p0.x + bi0.x, p0.y + bi0.y,
                                p1.x + bi0.z, p1.y + bi0.w);
        float4 c1 = make_float4(p2.x + bi1.x, p2.y + bi1.y,
                                p3.x + bi1.z, p3.y + bi1.w);
        if (RELU) {
            c0.x = fmaxf(c0.x, 0.f); c0.y = fmaxf(c0.y, 0.f);
            c0.z = fmaxf(c0.z, 0.f); c0.w = fmaxf(c0.w, 0.f);
            c1.x = fmaxf(c1.x, 0.f); c1.y = fmaxf(c1.y, 0.f);
            c1.z = fmaxf(c1.z, 0.f); c1.w = fmaxf(c1.w, 0.f);
        }
        *(float4*)(C + (size_t)gm * N + nc0) = c0;
        *(float4*)(C + (size_t)gm * N + nc1) = c1;
    }
}

// ---------------- mean pooling (batch is sorted -> segmented, no atomics) ---
__global__ void k_pool(const int* __restrict__ batch) {
    int g = blockIdx.x;
    int t = threadIdx.x;
    // lower_bound(g)
    int lo = 0, hi = NN;
    while (lo < hi) { int mid = (lo + hi) >> 1; if (batch[mid] < g) lo = mid + 1; else hi = mid; }
    int s = lo;
    // lower_bound(g+1)
    hi = NN;
    while (lo < hi) { int mid = (lo + hi) >> 1; if (batch[mid] < g + 1) lo = mid + 1; else hi = mid; }
    int e = lo;
    float4 sum = make_float4(0.f, 0.f, 0.f, 0.f);
    for (int v = s; v < e; v++) {
        float4 hv = ((const float4*)(g_h + (size_t)v * D))[t];
        sum.x += hv.x; sum.y += hv.y; sum.z += hv.z; sum.w += hv.w;
    }
    float inv = (e > s) ? 1.0f / (float)(e - s) : 0.0f;
    ((float4*)(g_pooled + (size_t)g * D))[t] =
        make_float4(sum.x * inv, sum.y * inv, sum.z * inv, sum.w * inv);
}

// ---------------- launch --------------------------------------------------
extern "C" void kernel_launch(void* const* d_in, const int* in_sizes, int n_in,
                              void* d_out, int out_size) {
    const int*   x    = (const int*)d_in[0];
    const int*   ei   = (const int*)d_in[1];
    const int*   ea   = (const int*)d_in[2];
    const int*   bat  = (const int*)d_in[3];
    const float* ae1  = (const float*)d_in[4];
    const float* ae2  = (const float*)d_in[5];
    const float* be1  = (const float*)d_in[6];
    const float* be2  = (const float*)d_in[7];
    const float* W1   = (const float*)d_in[8];
    const float* b1   = (const float*)d_in[9];
    const float* W2   = (const float*)d_in[10];
    const float* b2   = (const float*)d_in[11];
    const float* pW1  = (const float*)d_in[12];
    const float* pb1  = (const float*)d_in[13];
    const float* pW2  = (const float*)d_in[14];
    const float* pb2  = (const float*)d_in[15];
    float* out = (float*)d_out;

    float *p_agg, *p_hidden, *p_h, *p_pooled, *p_ptmp;
    cudaGetSymbolAddress((void**)&p_h, g_h);
    cudaGetSymbolAddress((void**)&p_agg, g_agg);
    cudaGetSymbolAddress((void**)&p_hidden, g_hidden);
    cudaGetSymbolAddress((void**)&p_pooled, g_pooled);
    cudaGetSymbolAddress((void**)&p_ptmp, g_ptmp);

    k_atom<<<NN, 128>>>(x, ae1, ae2);

    for (int l = 0; l < NL; l++) {
        const float* bl1 = be1 + (size_t)l * 8 * D;
        const float* bl2 = be2 + (size_t)l * 4 * D;
        k_init_agg<<<NN, 128>>>(bl1, bl2);
        k_scatter<<<NE, 128>>>(ei, ea, bl1, bl2);

        // hidden = relu(agg @ W1[l] + b1[l])   [NN, 1024]
        dim3 g1((NN + BM - 1) / BM, HID / BN);
        k_gemm<true><<<g1, 256>>>(p_agg, W1 + (size_t)l * D * HID,
                                  b1 + (size_t)l * HID, p_hidden, NN, HID, D);
        // h = hidden @ W2[l] + b2[l] (+relu except last layer)   [NN, 512]
        dim3 g2((NN + BM - 1) / BM, D / BN);
        if (l < NL - 1)
            k_gemm<true><<<g2, 256>>>(p_hidden, W2 + (size_t)l * HID * D,
                                      b2 + (size_t)l * D, p_h, NN, D, HID);
        else
            k_gemm<false><<<g2, 256>>>(p_hidden, W2 + (size_t)l * HID * D,
                                       b2 + (size_t)l * D, p_h, NN, D, HID);
    }

    // mean pool per graph
    k_pool<<<NG, 128>>>(bat);

    // projection head: out = relu(pooled @ pW1 + pb1) @ pW2 + pb2
    dim3 gp((NG + BM - 1) / BM, D / BN);
    k_gemm<true><<<gp, 256>>>(p_pooled, pW1, pb1, p_ptmp, NG, D, D);
    k_gemm<false><<<gp, 256>>>(p_ptmp, pW2, pb2, out, NG, D, D);
}

// round 3
// speedup vs baseline: 2.0895x; 2.0895x over previous
#include <cuda_runtime.h>
#include <cuda_bf16.h>
#include <cstdint>

#define D        512
#define NN       50000
#define NE       200000
#define NG       2048
#define NL       5
#define HID      1024

// ---------------- scratch (device globals; no allocations allowed) ----------
__device__ float g_h[(size_t)NN * D];
__device__ float g_agg[(size_t)NN * D];
__device__ float g_hidden[(size_t)NN * HID];
__device__ float g_pooled[(size_t)NG * D];
__device__ float g_ptmp[(size_t)NG * D];
// transposed + bf16-split weights [N, K], max 1024x512
__device__ __nv_bfloat16 g_wthi[(size_t)HID * D];
__device__ __nv_bfloat16 g_wtlo[(size_t)HID * D];

// ================= helpers ==================================================
__device__ __forceinline__ uint32_t s2u(const void* p) {
    uint32_t a;
    asm("{ .reg .u64 t; cvta.to.shared.u64 t, %1; cvt.u32.u64 %0, t; }"
        : "=r"(a) : "l"(p));
    return a;
}
__device__ __forceinline__ uint32_t lds32(uint32_t a) {
    uint32_t v;
    asm volatile("ld.shared.b32 %0, [%1];" : "=r"(v) : "r"(a));
    return v;
}
__device__ __forceinline__ void cp16(uint32_t dst, const void* src) {
    asm volatile("cp.async.ca.shared.global [%0], [%1], 16;"
                 :: "r"(dst), "l"(src) : "memory");
}
__device__ __forceinline__ void mma_bf16(float* c, const uint32_t* a,
                                         const uint32_t* b) {
    asm volatile(
        "mma.sync.aligned.m16n8k16.row.col.f32.bf16.bf16.f32 "
        "{%0,%1,%2,%3}, {%4,%5,%6,%7}, {%8,%9}, {%0,%1,%2,%3};"
        : "+f"(c[0]), "+f"(c[1]), "+f"(c[2]), "+f"(c[3])
        : "r"(a[0]), "r"(a[1]), "r"(a[2]), "r"(a[3]), "r"(b[0]), "r"(b[1]));
}

// ================= atom encoder / message passing ===========================
__global__ void k_atom(const int* __restrict__ x,
                       const float* __restrict__ e1,
                       const float* __restrict__ e2) {
    int v = blockIdx.x, t = threadIdx.x;
    int a = x[2 * v], c = x[2 * v + 1];
    float4 u = ((const float4*)(e1 + (size_t)a * D))[t];
    float4 w = ((const float4*)(e2 + (size_t)c * D))[t];
    ((float4*)(g_h + (size_t)v * D))[t] =
        make_float4(u.x + w.x, u.y + w.y, u.z + w.z, u.w + w.w);
}

__global__ void k_init_agg(const float* __restrict__ be1,
                           const float* __restrict__ be2) {
    int v = blockIdx.x, t = threadIdx.x;
    float4 l1 = ((const float4*)(be1 + 6 * D))[t];
    float4 l2 = ((const float4*)(be2 + 3 * D))[t];
    float4 hv = ((const float4*)(g_h + (size_t)v * D))[t];
    ((float4*)(g_agg + (size_t)v * D))[t] =
        make_float4(hv.x + l1.x + l2.x, hv.y + l1.y + l2.y,
                    hv.z + l1.z + l2.z, hv.w + l1.w + l2.w);
}

__global__ void k_scatter(const int* __restrict__ ei,
                          const int* __restrict__ ea,
                          const float* __restrict__ be1,
                          const float* __restrict__ be2) {
    int e = blockIdx.x, t = threadIdx.x;
    int src = ei[e];
    int dst = ei[NE + e];
    int a0 = ea[2 * e], a1 = ea[2 * e + 1];
    float4 hv = ((const float4*)(g_h + (size_t)src * D))[t];
    float4 v1 = ((const float4*)(be1 + (size_t)a0 * D))[t];
    float4 v2 = ((const float4*)(be2 + (size_t)a1 * D))[t];
    float* p = g_agg + (size_t)dst * D + t * 4;
    atomicAdd(p + 0, hv.x + v1.x + v2.x);
    atomicAdd(p + 1, hv.y + v1.y + v2.y);
    atomicAdd(p + 2, hv.z + v1.z + v2.z);
    atomicAdd(p + 3, hv.w + v1.w + v2.w);
}

// ================= weight transpose + bf16 split ============================
__global__ void k_prepW(const float* __restrict__ W, int K, int N) {
    __shared__ float t[32][33];
    int n0 = blockIdx.x * 32, k0 = blockIdx.y * 32;
    int tx = threadIdx.x, ty = threadIdx.y;   // 32 x 8
#pragma unroll
    for (int i = 0; i < 4; i++)
        t[ty + i * 8][tx] = W[(size_t)(k0 + ty + i * 8) * N + n0 + tx];
    __syncthreads();
#pragma unroll
    for (int i = 0; i < 4; i++) {
        int n = n0 + ty + i * 8, k = k0 + tx;
        float v = t[tx][ty + i * 8];
        __nv_bfloat16 h = __float2bfloat16_rn(v);
        g_wthi[(size_t)n * K + k] = h;
        g_wtlo[(size_t)n * K + k] = __float2bfloat16_rn(v - __bfloat162float(h));
    }
}

// ================= bf16-split mma.sync GEMM =================================
// C[M,N] = [relu](A[M,K] @ W + bias); W transposed+split in Bhi/Blo [N,K] bf16.
// CTA tile 128x128, BK=32, 128 threads (4 warps of 64x64), double-buffered.
#define KP    40                      // padded K stride (bf16 elems) -> no conflicts
#define MATE  (128 * KP)              // elems per matrix per stage
#define STAGE_E (4 * MATE)            // Ahi, Alo, Bhi, Blo
#define SMEM_G  (2 * STAGE_E * 2)     // bytes

__global__ void __launch_bounds__(128, 2)
k_gemm_mma(const float* __restrict__ A,
           const __nv_bfloat16* __restrict__ Bhi,
           const __nv_bfloat16* __restrict__ Blo,
           const float* __restrict__ bias,
           float* __restrict__ C,
           int M, int N, int K, int relu) {
    extern __shared__ __align__(16) __nv_bfloat16 sm[];
    const int tid = threadIdx.x;
    const int lane = tid & 31;
    const int wid = tid >> 5;
    const int g = lane >> 2, tg = lane & 3;
    const int wm = (wid >> 1) * 64, wn = (wid & 1) * 64;
    const int m0 = blockIdx.x * 128, n0 = blockIdx.y * 128;
    const int NC = K >> 5;

    const uint32_t sbase = s2u(sm);

    float acc[4][8][4];
#pragma unroll
    for (int i = 0; i < 4; i++)
#pragma unroll
        for (int j = 0; j < 8; j++)
#pragma unroll
            for (int k = 0; k < 4; k++) acc[i][j][k] = 0.f;

    // ---- loaders -----------------------------------------------------------
    auto ldgA = [&](int c, float4* pa) {
        const float* Ab = A + (size_t)m0 * K + c * 32;
#pragma unroll
        for (int i = 0; i < 8; i++) {
            int idx = tid + i * 128;
            int r = idx >> 3, c4 = idx & 7;
            pa[i] = (m0 + r < M) ? *(const float4*)(Ab + (size_t)r * K + c4 * 4)
                                 : make_float4(0.f, 0.f, 0.f, 0.f);
        }
    };
    auto stsA = [&](int st, const float4* pa) {
        __nv_bfloat16* ah = sm + st * STAGE_E;
        __nv_bfloat16* al = ah + MATE;
#pragma unroll
        for (int i = 0; i < 8; i++) {
            int idx = tid + i * 128;
            int r = idx >> 3, c4 = idx & 7;
            float4 v = pa[i];
            __nv_bfloat162 h0 = __floats2bfloat162_rn(v.x, v.y);
            __nv_bfloat162 h1 = __floats2bfloat162_rn(v.z, v.w);
            float2 f0 = __bfloat1622float2(h0), f1 = __bfloat1622float2(h1);
            __nv_bfloat162 l0 = __floats2bfloat162_rn(v.x - f0.x, v.y - f0.y);
            __nv_bfloat162 l1 = __floats2bfloat162_rn(v.z - f1.x, v.w - f1.y);
            int o = r * KP + c4 * 4;
            *(__nv_bfloat162*)(ah + o)     = h0;
            *(__nv_bfloat162*)(ah + o + 2) = h1;
            *(__nv_bfloat162*)(al + o)     = l0;
            *(__nv_bfloat162*)(al + o + 2) = l1;
        }
    };
    auto cpB = [&](int c, int st) {
        __nv_bfloat16* bh = sm + st * STAGE_E + 2 * MATE;
        __nv_bfloat16* bl = bh + MATE;
        const __nv_bfloat16* gh = Bhi + (size_t)n0 * K + c * 32;
        const __nv_bfloat16* gl = Blo + (size_t)n0 * K + c * 32;
#pragma unroll
        for (int i = 0; i < 4; i++) {
            int idx = tid + i * 128;
            int r = idx >> 2, c4 = idx & 3;
            int o = r * KP + c4 * 8;
            cp16(s2u(bh + o), gh + (size_t)r * K + c4 * 8);
            cp16(s2u(bl + o), gl + (size_t)r * K + c4 * 8);
        }
    };

    // ---- prologue ----------------------------------------------------------
    {
        float4 pa0[8];
        ldgA(0, pa0);
        cpB(0, 0);
        asm volatile("cp.async.commit_group;" ::: "memory");
        stsA(0, pa0);
    }

    // ---- mainloop ----------------------------------------------------------
    for (int c = 0; c < NC; c++) {
        const int cur = c & 1;
        const bool more = (c + 1 < NC);
        float4 pa[8];
        if (more) {
            ldgA(c + 1, pa);
            cpB(c + 1, (c + 1) & 1);
            asm volatile("cp.async.commit_group;" ::: "memory");
            asm volatile("cp.async.wait_group 1;" ::: "memory");
        } else {
            asm volatile("cp.async.wait_group 0;" ::: "memory");
        }
        __syncthreads();

        const uint32_t ahB = sbase + (cur * STAGE_E) * 2;
        const uint32_t alB = ahB + MATE * 2;
        const uint32_t bhB = ahB + 2 * MATE * 2;
        const uint32_t blB = ahB + 3 * MATE * 2;

#pragma unroll
        for (int ks = 0; ks < 32; ks += 16) {
            uint32_t bh[8][2], bl[8][2];
#pragma unroll
            for (int nt = 0; nt < 8; nt++) {
                uint32_t o = ((wn + nt * 8 + g) * KP + ks + tg * 2) * 2;
                bh[nt][0] = lds32(bhB + o);
                bh[nt][1] = lds32(bhB + o + 16);
                bl[nt][0] = lds32(blB + o);
                bl[nt][1] = lds32(blB + o + 16);
            }
#pragma unroll
            for (int mt = 0; mt < 4; mt++) {
                uint32_t o = ((wm + mt * 16 + g) * KP + ks + tg * 2) * 2;
                uint32_t ah[4], al[4];
                ah[0] = lds32(ahB + o);
                ah[1] = lds32(ahB + o + 8 * KP * 2);
                ah[2] = lds32(ahB + o + 16);
                ah[3] = lds32(ahB + o + 8 * KP * 2 + 16);
                al[0] = lds32(alB + o);
                al[1] = lds32(alB + o + 8 * KP * 2);
                al[2] = lds32(alB + o + 16);
                al[3] = lds32(alB + o + 8 * KP * 2 + 16);
#pragma unroll
                for (int nt = 0; nt < 8; nt++) {
                    mma_bf16(acc[mt][nt], ah, bh[nt]);
                    mma_bf16(acc[mt][nt], ah, bl[nt]);
                    mma_bf16(acc[mt][nt], al, bh[nt]);
                }
            }
        }
        __syncthreads();
        if (more) stsA((c + 1) & 1, pa);
    }

    // ---- epilogue ----------------------------------------------------------
#pragma unroll
    for (int mt = 0; mt < 4; mt++) {
        int r0 = m0 + wm + mt * 16 + g;
        int r1 = r0 + 8;
#pragma unroll
        for (int nt = 0; nt < 8; nt++) {
            int n = n0 + wn + nt * 8 + tg * 2;
            float2 bi = *(const float2*)(bias + n);
            float2 v0 = make_float2(acc[mt][nt][0] + bi.x, acc[mt][nt][1] + bi.y);
            float2 v1 = make_float2(acc[mt][nt][2] + bi.x, acc[mt][nt][3] + bi.y);
            if (relu) {
                v0.x = fmaxf(v0.x, 0.f); v0.y = fmaxf(v0.y, 0.f);
                v1.x = fmaxf(v1.x, 0.f); v1.y = fmaxf(v1.y, 0.f);
            }
            if (r0 < M) *(float2*)(C + (size_t)r0 * N + n) = v0;
            if (r1 < M) *(float2*)(C + (size_t)r1 * N + n) = v1;
        }
    }
}

// ================= mean pooling (batch sorted -> segmented) =================
__global__ void k_pool(const int* __restrict__ batch) {
    int g = blockIdx.x, t = threadIdx.x;
    int lo = 0, hi = NN;
    while (lo < hi) { int mid = (lo + hi) >> 1; if (batch[mid] < g) lo = mid + 1; else hi = mid; }
    int s = lo;
    hi = NN;
    while (lo < hi) { int mid = (lo + hi) >> 1; if (batch[mid] < g + 1) lo = mid + 1; else hi = mid; }
    int e = lo;
    float4 sum = make_float4(0.f, 0.f, 0.f, 0.f);
    for (int v = s; v < e; v++) {
        float4 hv = ((const float4*)(g_h + (size_t)v * D))[t];
        sum.x += hv.x; sum.y += hv.y; sum.z += hv.z; sum.w += hv.w;
    }
    float inv = (e > s) ? 1.0f / (float)(e - s) : 0.0f;
    ((float4*)(g_pooled + (size_t)g * D))[t] =
        make_float4(sum.x * inv, sum.y * inv, sum.z * inv, sum.w * inv);
}

// ================= launch ===================================================
static void gemm_mma(const float* A, const float* bias, float* C,
                     int M, int N, int K, int relu,
                     const __nv_bfloat16* wthi, const __nv_bfloat16* wtlo) {
    dim3 grd((M + 127) / 128, N / 128);
    k_gemm_mma<<<grd, 128, SMEM_G>>>(A, wthi, wtlo, bias, C, M, N, K, relu);
}

extern "C" void kernel_launch(void* const* d_in, const int* in_sizes, int n_in,
                              void* d_out, int out_size) {
    const int*   x   = (const int*)d_in[0];
    const int*   ei  = (const int*)d_in[1];
    const int*   ea  = (const int*)d_in[2];
    const int*   bat = (const int*)d_in[3];
    const float* ae1 = (const float*)d_in[4];
    const float* ae2 = (const float*)d_in[5];
    const float* be1 = (const float*)d_in[6];
    const float* be2 = (const float*)d_in[7];
    const float* W1  = (const float*)d_in[8];
    const float* b1  = (const float*)d_in[9];
    const float* W2  = (const float*)d_in[10];
    const float* b2  = (const float*)d_in[11];
    const float* pW1 = (const float*)d_in[12];
    const float* pb1 = (const float*)d_in[13];
    const float* pW2 = (const float*)d_in[14];
    const float* pb2 = (const float*)d_in[15];
    float* out = (float*)d_out;

    cudaFuncSetAttribute(k_gemm_mma,
                         cudaFuncAttributeMaxDynamicSharedMemorySize, SMEM_G);

    float *p_h, *p_agg, *p_hidden, *p_pooled, *p_ptmp;
    __nv_bfloat16 *p_wthi, *p_wtlo;
    cudaGetSymbolAddress((void**)&p_h, g_h);
    cudaGetSymbolAddress((void**)&p_agg, g_agg);
    cudaGetSymbolAddress((void**)&p_hidden, g_hidden);
    cudaGetSymbolAddress((void**)&p_pooled, g_pooled);
    cudaGetSymbolAddress((void**)&p_ptmp, g_ptmp);
    cudaGetSymbolAddress((void**)&p_wthi, g_wthi);
    cudaGetSymbolAddress((void**)&p_wtlo, g_wtlo);

    k_atom<<<NN, 128>>>(x, ae1, ae2);

    for (int l = 0; l < NL; l++) {
        const float* bl1 = be1 + (size_t)l * 8 * D;
        const float* bl2 = be2 + (size_t)l * 4 * D;
        k_init_agg<<<NN, 128>>>(bl1, bl2);
        k_scatter<<<NE, 128>>>(ei, ea, bl1, bl2);

        // hidden = relu(agg @ W1[l] + b1[l])
        k_prepW<<<dim3(HID / 32, D / 32), dim3(32, 8)>>>(W1 + (size_t)l * D * HID, D, HID);
        gemm_mma(p_agg, b1 + (size_t)l * HID, p_hidden, NN, HID, D, 1, p_wthi, p_wtlo);
        // h = hidden @ W2[l] + b2[l]  (+relu except last layer)
        k_prepW<<<dim3(D / 32, HID / 32), dim3(32, 8)>>>(W2 + (size_t)l * HID * D, HID, D);
        gemm_mma(p_hidden, b2 + (size_t)l * D, p_h, NN, D, HID, (l < NL - 1) ? 1 : 0,
                 p_wthi, p_wtlo);
    }

    k_pool<<<NG, 128>>>(bat);

    // projection head
    k_prepW<<<dim3(D / 32, D / 32), dim3(32, 8)>>>(pW1, D, D);
    gemm_mma(p_pooled, pb1, p_ptmp, NG, D, D, 1, p_wthi, p_wtlo);
    k_prepW<<<dim3(D / 32, D / 32), dim3(32, 8)>>>(pW2, D, D);
    gemm_mma(p_ptmp, pb2, out, NG, D, D, 0, p_wthi, p_wtlo);
}

// round 4
// speedup vs baseline: 2.3543x; 1.1267x over previous
#include <cuda_runtime.h>
#include <cuda_bf16.h>
#include <cstdint>

#define D        512
#define NN       50000
#define NE       200000
#define NG       2048
#define NL       5
#define HID      1024

// ---------------- scratch (device globals; no allocations allowed) ----------
__device__ float g_h[(size_t)NN * D];
__device__ float g_agg[(size_t)NN * D];
__device__ float g_hidden[(size_t)NN * HID];
__device__ float g_pooled[(size_t)NG * D];
__device__ float g_ptmp[(size_t)NG * D];
// transposed + bf16-split weights [N, K]; set 1: W1 (1024x512), set 2: W2 (512x1024)
__device__ __nv_bfloat16 g_w1hi[(size_t)HID * D];
__device__ __nv_bfloat16 g_w1lo[(size_t)HID * D];
__device__ __nv_bfloat16 g_w2hi[(size_t)HID * D];
__device__ __nv_bfloat16 g_w2lo[(size_t)HID * D];

// ================= helpers ==================================================
__device__ __forceinline__ uint32_t s2u(const void* p) {
    uint32_t a;
    asm("{ .reg .u64 t; cvta.to.shared.u64 t, %1; cvt.u32.u64 %0, t; }"
        : "=r"(a) : "l"(p));
    return a;
}
__device__ __forceinline__ void cp16(uint32_t dst, const void* src) {
    asm volatile("cp.async.ca.shared.global [%0], [%1], 16;"
                 :: "r"(dst), "l"(src) : "memory");
}
__device__ __forceinline__ void ldsm4(uint32_t* r, uint32_t a) {
    asm volatile("ldmatrix.sync.aligned.m8n8.x4.shared.b16 {%0,%1,%2,%3}, [%4];"
                 : "=r"(r[0]), "=r"(r[1]), "=r"(r[2]), "=r"(r[3]) : "r"(a));
}
__device__ __forceinline__ void mma_bf16(float* c, const uint32_t* a,
                                         const uint32_t* b) {
    asm volatile(
        "mma.sync.aligned.m16n8k16.row.col.f32.bf16.bf16.f32 "
        "{%0,%1,%2,%3}, {%4,%5,%6,%7}, {%8,%9}, {%0,%1,%2,%3};"
        : "+f"(c[0]), "+f"(c[1]), "+f"(c[2]), "+f"(c[3])
        : "r"(a[0]), "r"(a[1]), "r"(a[2]), "r"(a[3]), "r"(b[0]), "r"(b[1]));
}
__device__ __forceinline__ void redv4(float* p, float x, float y, float z, float w) {
    asm volatile("red.global.add.v4.f32 [%0], {%1,%2,%3,%4};"
                 :: "l"(p), "f"(x), "f"(y), "f"(z), "f"(w) : "memory");
}

// ================= atom encoder / message passing ===========================
__global__ void k_atom(const int* __restrict__ x,
                       const float* __restrict__ e1,
                       const float* __restrict__ e2) {
    int v = blockIdx.x, t = threadIdx.x;
    int a = x[2 * v], c = x[2 * v + 1];
    float4 u = ((const float4*)(e1 + (size_t)a * D))[t];
    float4 w = ((const float4*)(e2 + (size_t)c * D))[t];
    ((float4*)(g_h + (size_t)v * D))[t] =
        make_float4(u.x + w.x, u.y + w.y, u.z + w.z, u.w + w.w);
}

__global__ void k_init_agg(const float* __restrict__ be1,
                           const float* __restrict__ be2) {
    int v = blockIdx.x, t = threadIdx.x;
    float4 l1 = ((const float4*)(be1 + 6 * D))[t];
    float4 l2 = ((const float4*)(be2 + 3 * D))[t];
    float4 hv = ((const float4*)(g_h + (size_t)v * D))[t];
    ((float4*)(g_agg + (size_t)v * D))[t] =
        make_float4(hv.x + l1.x + l2.x, hv.y + l1.y + l2.y,
                    hv.z + l1.z + l2.z, hv.w + l1.w + l2.w);
}

__global__ void k_scatter(const int* __restrict__ ei,
                          const int* __restrict__ ea,
                          const float* __restrict__ be1,
                          const float* __restrict__ be2) {
    int e = blockIdx.x, t = threadIdx.x;
    int src = ei[e];
    int dst = ei[NE + e];
    int a0 = ea[2 * e], a1 = ea[2 * e + 1];
    float4 hv = ((const float4*)(g_h + (size_t)src * D))[t];
    float4 v1 = ((const float4*)(be1 + (size_t)a0 * D))[t];
    float4 v2 = ((const float4*)(be2 + (size_t)a1 * D))[t];
    float* p = g_agg + (size_t)dst * D + t * 4;
    redv4(p, hv.x + v1.x + v2.x, hv.y + v1.y + v2.y,
             hv.z + v1.z + v2.z, hv.w + v1.w + v2.w);
}

// ================= weight transpose + bf16 split ============================
__global__ void k_prepW(const float* __restrict__ W, int K, int N,
                        __nv_bfloat16* __restrict__ whi,
                        __nv_bfloat16* __restrict__ wlo) {
    __shared__ float t[32][33];
    int n0 = blockIdx.x * 32, k0 = blockIdx.y * 32;
    int tx = threadIdx.x, ty = threadIdx.y;   // 32 x 8
#pragma unroll
    for (int i = 0; i < 4; i++)
        t[ty + i * 8][tx] = W[(size_t)(k0 + ty + i * 8) * N + n0 + tx];
    __syncthreads();
#pragma unroll
    for (int i = 0; i < 4; i++) {
        int n = n0 + ty + i * 8, k = k0 + tx;
        float v = t[tx][ty + i * 8];
        __nv_bfloat16 h = __float2bfloat16_rn(v);
        whi[(size_t)n * K + k] = h;
        wlo[(size_t)n * K + k] = __float2bfloat16_rn(v - __bfloat162float(h));
    }
}

// ================= bf16-split mma.sync GEMM =================================
// C[M,N] = [relu](A[M,K] @ W + bias); W transposed+split in Bhi/Blo [N,K] bf16.
// CTA tile 128x128, BK=32, 128 threads (4 warps of 64x64), double-buffered,
// ldmatrix fragment loads.
#define KP    40                      // padded K stride (bf16 elems)
#define MATE  (128 * KP)
#define STAGE_E (4 * MATE)            // Ahi, Alo, Bhi, Blo
#define SMEM_G  (2 * STAGE_E * 2)     // bytes

__global__ void __launch_bounds__(128, 2)
k_gemm_mma(const float* __restrict__ A,
           const __nv_bfloat16* __restrict__ Bhi,
           const __nv_bfloat16* __restrict__ Blo,
           const float* __restrict__ bias,
           float* __restrict__ C,
           int M, int N, int K, int relu) {
    extern __shared__ __align__(16) __nv_bfloat16 sm[];
    const int tid = threadIdx.x;
    const int lane = tid & 31;
    const int wid = tid >> 5;
    const int g = lane >> 2, tg = lane & 3;
    const int wm = (wid >> 1) * 64, wn = (wid & 1) * 64;
    const int m0 = blockIdx.x * 128, n0 = blockIdx.y * 128;
    const int NC = K >> 5;

    const uint32_t sbase = s2u(sm);

    // ldmatrix per-lane address components
    const int lA_row = lane & 15;               // A: row within 16
    const int lA_k   = (lane >> 4) << 3;        // A: 0 or 8
    const int lB_n   = ((lane >> 4) << 3) + (lane & 7);  // B: n within 16
    const int lB_k   = ((lane >> 3) & 1) << 3;  // B: 0/8

    float acc[4][8][4];
#pragma unroll
    for (int i = 0; i < 4; i++)
#pragma unroll
        for (int j = 0; j < 8; j++)
#pragma unroll
            for (int k = 0; k < 4; k++) acc[i][j][k] = 0.f;

    auto ldgA = [&](int c, float4* pa) {
        const float* Ab = A + (size_t)m0 * K + c * 32;
#pragma unroll
        for (int i = 0; i < 8; i++) {
            int idx = tid + i * 128;
            int r = idx >> 3, c4 = idx & 7;
            pa[i] = (m0 + r < M) ? *(const float4*)(Ab + (size_t)r * K + c4 * 4)
                                 : make_float4(0.f, 0.f, 0.f, 0.f);
        }
    };
    auto stsA = [&](int st, const float4* pa) {
        __nv_bfloat16* ah = sm + st * STAGE_E;
        __nv_bfloat16* al = ah + MATE;
#pragma unroll
        for (int i = 0; i < 8; i++) {
            int idx = tid + i * 128;
            int r = idx >> 3, c4 = idx & 7;
            float4 v = pa[i];
            __nv_bfloat162 h0 = __floats2bfloat162_rn(v.x, v.y);
            __nv_bfloat162 h1 = __floats2bfloat162_rn(v.z, v.w);
            float2 f0 = __bfloat1622float2(h0), f1 = __bfloat1622float2(h1);
            __nv_bfloat162 l0 = __floats2bfloat162_rn(v.x - f0.x, v.y - f0.y);
            __nv_bfloat162 l1 = __floats2bfloat162_rn(v.z - f1.x, v.w - f1.y);
            int o = r * KP + c4 * 4;
            *(__nv_bfloat162*)(ah + o)     = h0;
            *(__nv_bfloat162*)(ah + o + 2) = h1;
            *(__nv_bfloat162*)(al + o)     = l0;
            *(__nv_bfloat162*)(al + o + 2) = l1;
        }
    };
    auto cpB = [&](int c, int st) {
        __nv_bfloat16* bh = sm + st * STAGE_E + 2 * MATE;
        __nv_bfloat16* bl = bh + MATE;
        const __nv_bfloat16* gh = Bhi + (size_t)n0 * K + c * 32;
        const __nv_bfloat16* gl = Blo + (size_t)n0 * K + c * 32;
#pragma unroll
        for (int i = 0; i < 4; i++) {
            int idx = tid + i * 128;
            int r = idx >> 2, c4 = idx & 3;
            int o = r * KP + c4 * 8;
            cp16(s2u(bh + o), gh + (size_t)r * K + c4 * 8);
            cp16(s2u(bl + o), gl + (size_t)r * K + c4 * 8);
        }
    };

    // ---- prologue ----------------------------------------------------------
    {
        float4 pa0[8];
        ldgA(0, pa0);
        cpB(0, 0);
        asm volatile("cp.async.commit_group;" ::: "memory");
        stsA(0, pa0);
    }

    // ---- mainloop ----------------------------------------------------------
    for (int c = 0; c < NC; c++) {
        const int cur = c & 1;
        const bool more = (c + 1 < NC);
        float4 pa[8];
        if (more) {
            ldgA(c + 1, pa);
            cpB(c + 1, (c + 1) & 1);
            asm volatile("cp.async.commit_group;" ::: "memory");
            asm volatile("cp.async.wait_group 1;" ::: "memory");
        } else {
            asm volatile("cp.async.wait_group 0;" ::: "memory");
        }
        __syncthreads();

        const uint32_t ahB = sbase + (cur * STAGE_E) * 2;
        const uint32_t alB = ahB + MATE * 2;
        const uint32_t bhB = ahB + 2 * MATE * 2;
        const uint32_t blB = ahB + 3 * MATE * 2;

#pragma unroll
        for (int ks = 0; ks < 32; ks += 16) {
            // B fragments: 8 n-tiles, loaded 2 per ldmatrix.x4
            uint32_t bh[8][2], bl[8][2];
#pragma unroll
            for (int np = 0; np < 4; np++) {
                uint32_t o = (uint32_t)(((wn + np * 16 + lB_n) * KP + ks + lB_k) * 2);
                uint32_t r[4];
                ldsm4(r, bhB + o);
                bh[np * 2][0] = r[0]; bh[np * 2][1] = r[1];
                bh[np * 2 + 1][0] = r[2]; bh[np * 2 + 1][1] = r[3];
                ldsm4(r, blB + o);
                bl[np * 2][0] = r[0]; bl[np * 2][1] = r[1];
                bl[np * 2 + 1][0] = r[2]; bl[np * 2 + 1][1] = r[3];
            }
#pragma unroll
            for (int mt = 0; mt < 4; mt++) {
                uint32_t o = (uint32_t)(((wm + mt * 16 + lA_row) * KP + ks + lA_k) * 2);
                uint32_t ah[4], al[4];
                ldsm4(ah, ahB + o);
                ldsm4(al, alB + o);
#pragma unroll
                for (int nt = 0; nt < 8; nt++) {
                    mma_bf16(acc[mt][nt], ah, bh[nt]);
                    mma_bf16(acc[mt][nt], ah, bl[nt]);
                    mma_bf16(acc[mt][nt], al, bh[nt]);
                }
            }
        }
        __syncthreads();
        if (more) stsA((c + 1) & 1, pa);
    }

    // ---- epilogue ----------------------------------------------------------
#pragma unroll
    for (int mt = 0; mt < 4; mt++) {
        int r0 = m0 + wm + mt * 16 + g;
        int r1 = r0 + 8;
#pragma unroll
        for (int nt = 0; nt < 8; nt++) {
            int n = n0 + wn + nt * 8 + tg * 2;
            float2 bi = *(const float2*)(bias + n);
            float2 v0 = make_float2(acc[mt][nt][0] + bi.x, acc[mt][nt][1] + bi.y);
            float2 v1 = make_float2(acc[mt][nt][2] + bi.x, acc[mt][nt][3] + bi.y);
            if (relu) {
                v0.x = fmaxf(v0.x, 0.f); v0.y = fmaxf(v0.y, 0.f);
                v1.x = fmaxf(v1.x, 0.f); v1.y = fmaxf(v1.y, 0.f);
            }
            if (r0 < M) *(float2*)(C + (size_t)r0 * N + n) = v0;
            if (r1 < M) *(float2*)(C + (size_t)r1 * N + n) = v1;
        }
    }
}

// ================= mean pooling (batch sorted -> segmented) =================
__global__ void k_pool(const int* __restrict__ batch) {
    int g = blockIdx.x, t = threadIdx.x;
    int lo = 0, hi = NN;
    while (lo < hi) { int mid = (lo + hi) >> 1; if (batch[mid] < g) lo = mid + 1; else hi = mid; }
    int s = lo;
    hi = NN;
    while (lo < hi) { int mid = (lo + hi) >> 1; if (batch[mid] < g + 1) lo = mid + 1; else hi = mid; }
    int e = lo;
    float4 sum = make_float4(0.f, 0.f, 0.f, 0.f);
    for (int v = s; v < e; v++) {
        float4 hv = ((const float4*)(g_h + (size_t)v * D))[t];
        sum.x += hv.x; sum.y += hv.y; sum.z += hv.z; sum.w += hv.w;
    }
    float inv = (e > s) ? 1.0f / (float)(e - s) : 0.0f;
    ((float4*)(g_pooled + (size_t)g * D))[t] =
        make_float4(sum.x * inv, sum.y * inv, sum.z * inv, sum.w * inv);
}

// ================= launch ===================================================
static void gemm_mma(const float* A, const float* bias, float* C,
                     int M, int N, int K, int relu,
                     const __nv_bfloat16* whi, const __nv_bfloat16* wlo) {
    dim3 grd((M + 127) / 128, N / 128);
    k_gemm_mma<<<grd, 128, SMEM_G>>>(A, whi, wlo, bias, C, M, N, K, relu);
}

extern "C" void kernel_launch(void* const* d_in, const int* in_sizes, int n_in,
                              void* d_out, int out_size) {
    const int*   x   = (const int*)d_in[0];
    const int*   ei  = (const int*)d_in[1];
    const int*   ea  = (const int*)d_in[2];
    const int*   bat = (const int*)d_in[3];
    const float* ae1 = (const float*)d_in[4];
    const float* ae2 = (const float*)d_in[5];
    const float* be1 = (const float*)d_in[6];
    const float* be2 = (const float*)d_in[7];
    const float* W1  = (const float*)d_in[8];
    const float* b1  = (const float*)d_in[9];
    const float* W2  = (const float*)d_in[10];
    const float* b2  = (const float*)d_in[11];
    const float* pW1 = (const float*)d_in[12];
    const float* pb1 = (const float*)d_in[13];
    const float* pW2 = (const float*)d_in[14];
    const float* pb2 = (const float*)d_in[15];
    float* out = (float*)d_out;

    cudaFuncSetAttribute(k_gemm_mma,
                         cudaFuncAttributeMaxDynamicSharedMemorySize, SMEM_G);

    float *p_h, *p_agg, *p_hidden, *p_pooled, *p_ptmp;
    __nv_bfloat16 *p_w1hi, *p_w1lo, *p_w2hi, *p_w2lo;
    cudaGetSymbolAddress((void**)&p_h, g_h);
    cudaGetSymbolAddress((void**)&p_agg, g_agg);
    cudaGetSymbolAddress((void**)&p_hidden, g_hidden);
    cudaGetSymbolAddress((void**)&p_pooled, g_pooled);
    cudaGetSymbolAddress((void**)&p_ptmp, g_ptmp);
    cudaGetSymbolAddress((void**)&p_w1hi, g_w1hi);
    cudaGetSymbolAddress((void**)&p_w1lo, g_w1lo);
    cudaGetSymbolAddress((void**)&p_w2hi, g_w2hi);
    cudaGetSymbolAddress((void**)&p_w2lo, g_w2lo);

    k_atom<<<NN, 128>>>(x, ae1, ae2);   // launch 0

    for (int l = 0; l < NL; l++) {
        const float* bl1 = be1 + (size_t)l * 8 * D;
        const float* bl2 = be2 + (size_t)l * 4 * D;
        k_init_agg<<<NN, 128>>>(bl1, bl2);                       // l=0: launch 1
        k_scatter<<<NE, 128>>>(ei, ea, bl1, bl2);                // l=0: launch 2
        // prep both weight splits BEFORE gemm1 (makes gemm1 launch #5 for ncu)
        k_prepW<<<dim3(HID / 32, D / 32), dim3(32, 8)>>>(
            W1 + (size_t)l * D * HID, D, HID, p_w1hi, p_w1lo);   // launch 3
        k_prepW<<<dim3(D / 32, HID / 32), dim3(32, 8)>>>(
            W2 + (size_t)l * HID * D, HID, D, p_w2hi, p_w2lo);   // launch 4
        gemm_mma(p_agg, b1 + (size_t)l * HID, p_hidden, NN, HID, D, 1,
                 p_w1hi, p_w1lo);                                // launch 5
        gemm_mma(p_hidden, b2 + (size_t)l * D, p_h, NN, D, HID,
                 (l < NL - 1) ? 1 : 0, p_w2hi, p_w2lo);
    }

    k_pool<<<NG, 128>>>(bat);

    // projection head (reuse weight-set 1 buffers)
    k_prepW<<<dim3(D / 32, D / 32), dim3(32, 8)>>>(pW1, D, D, p_w1hi, p_w1lo);
    gemm_mma(p_pooled, pb1, p_ptmp, NG, D, D, 1, p_w1hi, p_w1lo);
    k_prepW<<<dim3(D / 32, D / 32), dim3(32, 8)>>>(pW2, D, D, p_w2hi, p_w2lo);
    gemm_mma(p_ptmp, pb2, out, NG, D, D, 0, p_w2hi, p_w2lo);
}